// round 8
// baseline (speedup 1.0000x reference)
#include <cuda_runtime.h>
#include <stdint.h>

// Problem constants (fixed by the dataset)
#define T_  500
#define B_  16
#define S_  256
#define P_  128
#define L_  16

#define STR   33     // sl row stride (words): fill stride-33 & gather lane-consecutive both conflict-free
#define OST   129    // output-transpose row stride: banks (lane + p) -> conflict-free
#define SEGB  48     // bytes per (p, s-half) list segment (cap 48; mean 12.8, sigma 3.4 -> >10 sigma)
#define PH    64     // phonemes per CTA
#define PADV (-3.402823466e38f)

// Membership bitmask, u16 halves: [lang][p][16]. u32 view gives word w at index
// (lang*P+p)*8+w (little-endian halves 2w|2w+1 = s bits w*32..w*32+31).
__device__ unsigned short g_bitsH[L_ * P_ * 16];

// ---------------------------------------------------------------------------
// Build: CTA = (lang, 16-s chunk) -> 256 CTAs x 128 threads. Thread builds one
// 16-bit membership half-word from 16 independent coalesced loads. (~1.8us)
// Pure function of mats -> safe to replay every graph iteration.
// ---------------------------------------------------------------------------
__global__ __launch_bounds__(P_) void build_bits_kernel(const float* __restrict__ mats) {
    const int l  = blockIdx.x >> 4;
    const int hh = blockIdx.x & 15;
    const int p  = threadIdx.x;

    const float* base = mats + ((size_t)l * S_ + hh * 16) * P_ + p;

    uint32_t acc0 = 0, acc1 = 0;
    #pragma unroll
    for (int j = 0; j < 8; ++j) {
        float v0 = base[(size_t)(2 * j)     * P_];   // coalesced across p
        float v1 = base[(size_t)(2 * j + 1) * P_];
        acc0 |= (v0 != 0.0f ? 1u : 0u) << (2 * j);
        acc1 |= (v1 != 0.0f ? 1u : 0u) << (2 * j + 1);
    }
    g_bitsH[((l * P_ + p) << 4) + hh] = (unsigned short)(acc0 | acc1);
}

// ---------------------------------------------------------------------------
// Main: CTA = (32-t tile, b, p-half of 64), 512 threads = 16 warps.
// lane = t; warp handles 4 p's with a WARP-UNIFORM packed-u8 index list:
// every gather is LDS.32 at sl[s*33+lane] -> 32 useful updates per single
// conflict-free wavefront, zero divergence. Lists built in-CTA from bitmask.
// ---------------------------------------------------------------------------
__global__ __launch_bounds__(512) void allophone_map_kernel(
    const float* __restrict__ logits,      // [T, B, S]
    const int*   __restrict__ lang_ids,    // [B]
    float*       __restrict__ out)         // [T, B, P]
{
    __shared__ float          sl[S_ * STR];        // 33,792 B (reused as so[32*OST] later)
    __shared__ unsigned char  slist[2 * PH * SEGB];// 6,144 B packed u8 lists
    __shared__ int            swcnt[2 * PH];       // u32-word count per segment

    const int t0   = blockIdx.x * 32;
    const int b    = blockIdx.y;
    const int p0   = blockIdx.z * PH;
    const int tid  = threadIdx.x;
    const int lane = tid & 31;
    const int wid  = tid >> 5;

    const int lang = __ldg(lang_ids + b);

    // Phase A: fill logits tile. LDG coalesced (consecutive s); STS stride 33
    // across consecutive s -> conflict-free.
    #pragma unroll
    for (int it = 0; it < 16; ++it) {
        int i = it * 512 + tid;
        int s = i & (S_ - 1);
        int t = i >> 8;
        int te = t0 + t; if (te >= T_) te = T_ - 1;   // tail clamp (stores guarded)
        sl[s * STR + t] = logits[((size_t)te * B_ + b) * S_ + s];
    }

    // Phase A2: first 128 threads build packed u8 lists for (p_loc, s-half).
    // ~13-bit walks each; padded to a multiple of 4 by duplicating the last
    // index (idempotent under max).
    if (tid < 2 * PH) {
        int p_loc = tid & (PH - 1);
        int h     = tid >> 6;                       // s-half: words h*4..h*4+3
        int p     = p0 + p_loc;
        const uint32_t* gb = (const uint32_t*)g_bitsH + ((size_t)lang * P_ + p) * 8 + h * 4;
        unsigned char* dst = slist + (p_loc * 2 + h) * SEGB;
        int n = 0, last = 0;
        #pragma unroll
        for (int k = 0; k < 4; ++k) {
            uint32_t word = __ldg(gb + k);
            int sbase = (h * 4 + k) * 32;
            while (word) {
                int bit = __ffs(word) - 1;
                word &= word - 1;
                last = sbase + bit;
                dst[n++] = (unsigned char)last;
            }
        }
        while (n & 3) dst[n++] = (unsigned char)last;
        swcnt[p_loc * 2 + h] = n >> 2;              // u32 words
    }
    __syncthreads();

    // Phase B: warp-uniform gather. Warp wid -> p_loc = wid*4 + j.
    float acc[4];
    #pragma unroll
    for (int j = 0; j < 4; ++j) {
        int p_loc = wid * 4 + j;
        float a0 = PADV, a1 = PADV;
        #pragma unroll
        for (int h = 0; h < 2; ++h) {
            int seg = p_loc * 2 + h;
            int nw  = swcnt[seg];                   // uniform
            const uint32_t* lw = (const uint32_t*)(slist + seg * SEGB);
            for (int k = 0; k < nw; ++k) {
                uint32_t word = lw[k];              // broadcast LDS (uniform addr)
                int s0 =  word        & 255;
                int s1 = (word >>  8) & 255;
                int s2 = (word >> 16) & 255;
                int s3 =  word >> 24;
                a0 = fmaxf(a0, sl[s0 * STR + lane]); // conflict-free, 32 useful/wavefront
                a1 = fmaxf(a1, sl[s1 * STR + lane]);
                a0 = fmaxf(a0, sl[s2 * STR + lane]);
                a1 = fmaxf(a1, sl[s3 * STR + lane]);
            }
        }
        acc[j] = fmaxf(a0, a1);
    }
    __syncthreads();   // all sl reads done before reuse

    // Phase C: transpose through reused smem, then coalesced stores.
    float* so = sl;                                  // 32*129 floats < sl capacity
    #pragma unroll
    for (int j = 0; j < 4; ++j) {
        int p_loc = wid * 4 + j;
        so[lane * OST + p_loc] = acc[j];             // banks (lane+p_loc): distinct
    }
    __syncthreads();

    #pragma unroll
    for (int it = 0; it < 4; ++it) {
        int i  = it * 512 + tid;
        int t  = i >> 6;
        int pc = i & (PH - 1);
        int tt = t0 + t;
        if (tt < T_)
            out[((size_t)tt * B_ + b) * P_ + p0 + pc] = so[t * OST + pc];
    }
}

// ---------------------------------------------------------------------------
extern "C" void kernel_launch(void* const* d_in, const int* in_sizes, int n_in,
                              void* d_out, int out_size) {
    const float* logits = (const float*)d_in[0];   // [T,B,S] f32
    const int*   langs  = (const int*)  d_in[1];   // [B] i32
    const float* mats   = (const float*)d_in[2];   // [L,S,P] f32
    // d_in[3] (mask) is redundant: mask == (mats == 0)

    build_bits_kernel<<<L_ * 16, P_>>>(mats);      // 256 CTAs

    dim3 grid((T_ + 31) / 32, B_, 2);              // 16 x 16 x 2 = 512 CTAs
    allophone_map_kernel<<<grid, 512>>>(logits, langs, (float*)d_out);
}